// round 2
// baseline (speedup 1.0000x reference)
#include <cuda_runtime.h>

#define NPOINTS 131072
#define INF 512
#define NC 64
#define ROWSTRIDE 513   // 512 features + 1 case id per row of x
#define RBLOCKS 148     // point tiles for the reduction
#define FCHUNK 256      // features per reduce block

// -------- device scratch (static: no allocations allowed) --------
__device__ float g_part[RBLOCKS][NC][INF];     // per-tile partial sums (~19.4 MB)
__device__ float g_pcnt[RBLOCKS][NC];          // per-tile case counts
__device__ __align__(16) float g_hbuf[4][NC * INF];  // h0(mean), h1, h2, h3(final)
__device__ float g_scale[2 * INF];             // g / ||V_row|| for layers 0,1
__device__ float g_Wt[3][INF * INF];           // scaled transposed weights (k-major)

// ============================================================================
// Stage 1: per-case partial sums. All 256 threads handle the SAME point each
// step -> thread t exclusively owns feature lane t of the smem accumulator,
// so no atomics and no races. Unroll 8 points for memory-level parallelism.
// ============================================================================
__global__ void reduce_kernel(const float* __restrict__ x) {
    extern __shared__ float sacc[];            // NC*FCHUNK accum + NC counts
    float* cnt = sacc + NC * FCHUNK;
    const int chunk = blockIdx.x;              // 0..1 -> feature half
    const int pt    = blockIdx.y;              // 0..RBLOCKS-1 -> point tile
    const int t     = threadIdx.x;             // 0..255
    const int cbase = chunk * FCHUNK;
    const bool count_owner = (chunk == 0 && t == 0);

    for (int i = t; i < NC * FCHUNK; i += 256) sacc[i] = 0.f;
    if (chunk == 0 && t < NC) cnt[t] = 0.f;
    __syncthreads();

    const int per = (NPOINTS + RBLOCKS - 1) / RBLOCKS;   // 886
    int p0 = pt * per;
    int p1 = p0 + per; if (p1 > NPOINTS) p1 = NPOINTS;

    int p = p0;
    for (; p + 8 <= p1; p += 8) {
        float v[8]; int c[8];
#pragma unroll
        for (int i = 0; i < 8; i++) {
            const float* row = x + (size_t)(p + i) * ROWSTRIDE;
            v[i] = row[cbase + t];
            c[i] = __float2int_rn(row[INF]);   // cid is an exact small integer
        }
#pragma unroll
        for (int i = 0; i < 8; i++) sacc[c[i] * FCHUNK + t] += v[i];
        if (count_owner) {
#pragma unroll
            for (int i = 0; i < 8; i++) cnt[c[i]] += 1.f;
        }
    }
    for (; p < p1; p++) {
        const float* row = x + (size_t)p * ROWSTRIDE;
        int c = __float2int_rn(row[INF]);
        sacc[c * FCHUNK + t] += row[cbase + t];
        if (count_owner) cnt[c] += 1.f;
    }
    __syncthreads();

    // dense partial store: no atomics, no init kernel needed
    for (int i = t; i < NC * FCHUNK; i += 256) {
        int c = i >> 8;          // i / FCHUNK
        int f = i & (FCHUNK - 1);
        g_part[pt][c][cbase + f] = sacc[i];
    }
    if (chunk == 0 && t < NC) g_pcnt[pt][t] = cnt[t];
}

// ============================================================================
// Stage 2: reduce partials across point tiles, divide by (clamped) counts.
// grid 64 blocks (one per case) x 512 threads (one per feature).
// ============================================================================
__global__ void mean_kernel() {
    const int c = blockIdx.x;
    const int f = threadIdx.x;
    float s = 0.f;
    for (int pt = 0; pt < RBLOCKS; pt++) s += g_part[pt][c][f];

    __shared__ float cs;
    if (f < 32) {
        float cn = 0.f;
        for (int pt = f; pt < RBLOCKS; pt += 32) cn += g_pcnt[pt][c];
        for (int off = 16; off; off >>= 1) cn += __shfl_down_sync(0xffffffffu, cn, off);
        if (f == 0) cs = fmaxf(cn, 1.f);
    }
    __syncthreads();
    g_hbuf[0][c * INF + f] = s / cs;
}

// ============================================================================
// Stage 3a: weight-norm row scales: g[o] / ||V[o]||.  1024 warps, one per row.
// ============================================================================
__global__ void norm_kernel(const float* __restrict__ V0, const float* __restrict__ g0,
                            const float* __restrict__ V1, const float* __restrict__ g1) {
    const int w    = blockIdx.x * (blockDim.x >> 5) + (threadIdx.x >> 5);
    const int lane = threadIdx.x & 31;
    const int layer = w >> 9;
    const int o     = w & 511;
    const float* V = layer ? V1 : V0;
    const float* g = layer ? g1 : g0;
    float ss = 0.f;
    for (int k = lane; k < INF; k += 32) {
        float v = V[(size_t)o * INF + k];
        ss = fmaf(v, v, ss);
    }
    for (int off = 16; off; off >>= 1) ss += __shfl_down_sync(0xffffffffu, ss, off);
    if (lane == 0) g_scale[layer * INF + o] = g[o] / sqrtf(ss);
}

// ============================================================================
// Stage 3b: build scaled transposed weights Wt[k][o] = V[o][k] * scale[o]
// (and plain transpose for Wf). 32x32 smem tiles.
// ============================================================================
__global__ void prep_wt(const float* __restrict__ V0, const float* __restrict__ V1,
                        const float* __restrict__ Wf) {
    __shared__ float tile[32][33];
    const int m = blockIdx.z;                        // 0: V0, 1: V1, 2: Wf
    const float* src = (m == 0) ? V0 : ((m == 1) ? V1 : Wf);
    const int ob = blockIdx.y * 32;
    const int kb = blockIdx.x * 32;
    const int tx = threadIdx.x, ty = threadIdx.y;
#pragma unroll
    for (int j = 0; j < 32; j += 8) {
        int o = ob + ty + j;
        float sc = (m < 2) ? g_scale[m * INF + o] : 1.f;
        tile[ty + j][tx] = src[(size_t)o * INF + kb + tx] * sc;
    }
    __syncthreads();
#pragma unroll
    for (int j = 0; j < 32; j += 8) {
        g_Wt[m][(size_t)(kb + ty + j) * INF + ob + tx] = tile[tx][ty + j];
    }
}

// ============================================================================
// Stage 4: tiny GEMM  h_out[c][o] = act( sum_k h_in[c][k] * Wt[k][o] + b[o] ).
// grid (16 o-tiles x 2 c-tiles), 256 threads. Warp = 32 outs x 4 cases,
// h tile staged in smem (broadcast LDS), weight reads coalesced LDG.
// ============================================================================
__global__ void gemm_kernel(int stage, const float* __restrict__ bias, int silu) {
    __shared__ float hs[32 * 128];
    const int t = threadIdx.x;
    const int lane = t & 31, w = t >> 5;
    const int obase = blockIdx.x * 32;
    const int cbase = blockIdx.y * 32;
    const int o = obase + lane;
    const float* hin  = g_hbuf[stage];
    float*       hout = g_hbuf[stage + 1];
    const float* Wt   = g_Wt[stage];

    float acc[4] = {0.f, 0.f, 0.f, 0.f};
    for (int kc = 0; kc < 4; kc++) {
        for (int i = t; i < 32 * 128; i += 256) {
            int cc = i >> 7, kk = i & 127;
            hs[i] = hin[(cbase + cc) * INF + kc * 128 + kk];
        }
        __syncthreads();
        const float* wp = Wt + (size_t)(kc * 128) * INF + o;
#pragma unroll 8
        for (int kk = 0; kk < 128; kk++) {
            float wv = wp[(size_t)kk * INF];
#pragma unroll
            for (int i = 0; i < 4; i++)
                acc[i] = fmaf(hs[(w * 4 + i) * 128 + kk], wv, acc[i]);
        }
        __syncthreads();
    }
    const float b = bias[o];
#pragma unroll
    for (int i = 0; i < 4; i++) {
        float v = acc[i] + b;
        if (silu) v = v * (1.f / (1.f + __expf(-v)));
        hout[(cbase + w * 4 + i) * INF + o] = v;
    }
}

// ============================================================================
// Stage 5: scatter out[p][:] = h_final[cid[p]][:] with float4 stores.
// grid 1024 blocks x 128 points each; 256 threads = 2 points x 128 float4.
// ============================================================================
__global__ void scatter_kernel(const float* __restrict__ x, float* __restrict__ out) {
    const int t  = threadIdx.x;
    const int pl = t >> 7;          // 0 or 1
    const int f4 = t & 127;         // float4 index within a 512-float row
    const float4* h4 = (const float4*)g_hbuf[3];
    float4* o4 = (float4*)out;
    const int p0 = blockIdx.x * 128;
#pragma unroll 4
    for (int p = p0 + pl; p < p0 + 128; p += 2) {
        int c = __float2int_rn(__ldg(x + (size_t)p * ROWSTRIDE + INF));
        float4 v = h4[c * 128 + f4];
        o4[(size_t)p * 128 + f4] = v;
    }
}

// ============================================================================
extern "C" void kernel_launch(void* const* d_in, const int* in_sizes, int n_in,
                              void* d_out, int out_size) {
    const float* x  = (const float*)d_in[0];
    const float* V0 = (const float*)d_in[1];
    const float* g0 = (const float*)d_in[2];
    const float* b0 = (const float*)d_in[3];
    const float* V1 = (const float*)d_in[4];
    const float* g1 = (const float*)d_in[5];
    const float* b1 = (const float*)d_in[6];
    const float* Wf = (const float*)d_in[7];
    const float* bf = (const float*)d_in[8];
    float* out = (float*)d_out;

    const int red_smem = (NC * FCHUNK + NC) * (int)sizeof(float);   // 65792 B
    cudaFuncSetAttribute(reduce_kernel,
                         cudaFuncAttributeMaxDynamicSharedMemorySize, red_smem);

    reduce_kernel<<<dim3(2, RBLOCKS), 256, red_smem>>>(x);
    mean_kernel<<<NC, INF>>>();
    norm_kernel<<<128, 256>>>(V0, g0, V1, g1);
    prep_wt<<<dim3(16, 16, 3), dim3(32, 8)>>>(V0, V1, Wf);
    gemm_kernel<<<dim3(16, 2), 256>>>(0, b0, 1);
    gemm_kernel<<<dim3(16, 2), 256>>>(1, b1, 1);
    gemm_kernel<<<dim3(16, 2), 256>>>(2, bf, 0);
    scatter_kernel<<<1024, 256>>>(x, out);
}

// round 7
// speedup vs baseline: 1.0473x; 1.0473x over previous
#include <cuda_runtime.h>

#define NPOINTS 131072
#define INF 512
#define NC 64
#define ROWSTRIDE 513   // 512 features + 1 case id per row of x
#define RBLOCKS 222     // point tiles: grid (2 x 222) = 444 = 148 SMs x 3 CTAs
#define FCHUNK 256      // features per reduce block

// -------- device scratch (static: no allocations allowed) --------
__device__ float g_part[RBLOCKS][NC][INF];     // per-tile partial sums (~29 MB)
__device__ float g_pcnt[RBLOCKS][NC];          // per-tile case counts
__device__ int   g_cid[NPOINTS];               // compact case ids (for scatter)
__device__ __align__(16) float g_hbuf[4][NC * INF];  // h0(mean), h1, h2, h3(final)
__device__ float g_scale[2 * INF];             // g / ||V_row|| for layers 0,1
__device__ float g_Wt[3][INF * INF];           // scaled transposed weights (k-major)

// ============================================================================
// Stage 1: per-case partial sums. All 256 threads handle the SAME point each
// step -> thread t exclusively owns feature lane t of the smem accumulator,
// so no atomics and no races. Unroll 16 points with explicit batch arrays so
// all 32 LDGs issue before the smem RMW chain. x is read once -> streaming.
// chunk==1 blocks additionally persist cid to g_cid for the scatter stage.
// ============================================================================
__global__ void reduce_kernel(const float* __restrict__ x) {
    extern __shared__ float sacc[];            // NC*FCHUNK accum + NC counts
    float* cnt = sacc + NC * FCHUNK;
    const int chunk = blockIdx.x;              // 0..1 -> feature half
    const int pt    = blockIdx.y;              // 0..RBLOCKS-1 -> point tile
    const int t     = threadIdx.x;             // 0..255
    const int cbase = chunk * FCHUNK;
    const bool count_owner = (chunk == 0 && t == 0);
    const bool cid_owner   = (chunk == 1 && t == 0);

    for (int i = t; i < NC * FCHUNK; i += 256) sacc[i] = 0.f;
    if (chunk == 0 && t < NC) cnt[t] = 0.f;
    __syncthreads();

    const int per = (NPOINTS + RBLOCKS - 1) / RBLOCKS;   // 591
    int p0 = pt * per;
    int p1 = p0 + per; if (p1 > NPOINTS) p1 = NPOINTS;

    int p = p0;
    for (; p + 16 <= p1; p += 16) {
        float v[16]; int c[16];
#pragma unroll
        for (int i = 0; i < 16; i++) {
            const float* row = x + (size_t)(p + i) * ROWSTRIDE;
            v[i] = __ldcs(row + cbase + t);
            c[i] = __float2int_rn(__ldcs(row + INF));   // cid: exact small int
        }
#pragma unroll
        for (int i = 0; i < 16; i++) sacc[c[i] * FCHUNK + t] += v[i];
        if (count_owner) {
#pragma unroll
            for (int i = 0; i < 16; i++) cnt[c[i]] += 1.f;
        }
        if (cid_owner) {
#pragma unroll
            for (int i = 0; i < 16; i++) g_cid[p + i] = c[i];
        }
    }
    for (; p < p1; p++) {
        const float* row = x + (size_t)p * ROWSTRIDE;
        int c = __float2int_rn(__ldcs(row + INF));
        sacc[c * FCHUNK + t] += __ldcs(row + cbase + t);
        if (count_owner) cnt[c] += 1.f;
        if (cid_owner) g_cid[p] = c;
    }
    __syncthreads();

    // dense partial store: no atomics, no init kernel needed
    for (int i = t; i < NC * FCHUNK; i += 256) {
        int c = i >> 8;          // i / FCHUNK
        int f = i & (FCHUNK - 1);
        g_part[pt][c][cbase + f] = sacc[i];
    }
    if (chunk == 0 && t < NC) g_pcnt[pt][t] = cnt[t];
}

// ============================================================================
// Stage 2: reduce partials across point tiles, divide by (clamped) counts.
// grid 64 blocks (one per case) x 512 threads (one per feature).
// 4 independent accumulators guarantee MLP >= 4 on the partial loads.
// ============================================================================
__global__ void mean_kernel() {
    const int c = blockIdx.x;
    const int f = threadIdx.x;
    float s0 = 0.f, s1 = 0.f, s2 = 0.f, s3 = 0.f;
    int pt = 0;
    for (; pt + 4 <= RBLOCKS; pt += 4) {
        s0 += g_part[pt + 0][c][f];
        s1 += g_part[pt + 1][c][f];
        s2 += g_part[pt + 2][c][f];
        s3 += g_part[pt + 3][c][f];
    }
    for (; pt < RBLOCKS; pt++) s0 += g_part[pt][c][f];
    float s = (s0 + s1) + (s2 + s3);

    __shared__ float cs;
    if (f < 32) {
        float cn = 0.f;
        for (int q = f; q < RBLOCKS; q += 32) cn += g_pcnt[q][c];
        for (int off = 16; off; off >>= 1) cn += __shfl_down_sync(0xffffffffu, cn, off);
        if (f == 0) cs = fmaxf(cn, 1.f);
    }
    __syncthreads();
    g_hbuf[0][c * INF + f] = s / cs;
}

// ============================================================================
// Stage 3a: weight-norm row scales: g[o] / ||V[o]||.  1024 warps, one per row.
// ============================================================================
__global__ void norm_kernel(const float* __restrict__ V0, const float* __restrict__ g0,
                            const float* __restrict__ V1, const float* __restrict__ g1) {
    const int w    = blockIdx.x * (blockDim.x >> 5) + (threadIdx.x >> 5);
    const int lane = threadIdx.x & 31;
    const int layer = w >> 9;
    const int o     = w & 511;
    const float* V = layer ? V1 : V0;
    const float* g = layer ? g1 : g0;
    float ss = 0.f;
    for (int k = lane; k < INF; k += 32) {
        float v = V[(size_t)o * INF + k];
        ss = fmaf(v, v, ss);
    }
    for (int off = 16; off; off >>= 1) ss += __shfl_down_sync(0xffffffffu, ss, off);
    if (lane == 0) g_scale[layer * INF + o] = g[o] / sqrtf(ss);
}

// ============================================================================
// Stage 3b: build scaled transposed weights Wt[k][o] = V[o][k] * scale[o]
// (and plain transpose for Wf). 32x32 smem tiles. mbase selects matrices.
// ============================================================================
__global__ void prep_wt(const float* __restrict__ A, const float* __restrict__ B,
                        int mbase) {
    __shared__ float tile[32][33];
    const int m = mbase + blockIdx.z;                // matrix index 0..2
    const float* src = blockIdx.z ? B : A;
    const int ob = blockIdx.y * 32;
    const int kb = blockIdx.x * 32;
    const int tx = threadIdx.x, ty = threadIdx.y;
#pragma unroll
    for (int j = 0; j < 32; j += 8) {
        int o = ob + ty + j;
        float sc = (m < 2) ? g_scale[m * INF + o] : 1.f;
        tile[ty + j][tx] = src[(size_t)o * INF + kb + tx] * sc;
    }
    __syncthreads();
#pragma unroll
    for (int j = 0; j < 32; j += 8) {
        g_Wt[m][(size_t)(kb + ty + j) * INF + ob + tx] = tile[tx][ty + j];
    }
}

// ============================================================================
// Stage 4: tiny GEMM  h_out[c][o] = act( sum_k h_in[c][k] * Wt[k][o] + b[o] ).
// grid (16 o-tiles x 2 c-tiles), 256 threads. Warp = 32 outs x 4 cases,
// h tile staged in smem (broadcast LDS), weight reads coalesced LDG.
// ============================================================================
__global__ void gemm_kernel(int stage, const float* __restrict__ bias, int silu) {
    __shared__ float hs[32 * 128];
    const int t = threadIdx.x;
    const int lane = t & 31, w = t >> 5;
    const int obase = blockIdx.x * 32;
    const int cbase = blockIdx.y * 32;
    const int o = obase + lane;
    const float* hin  = g_hbuf[stage];
    float*       hout = g_hbuf[stage + 1];
    const float* Wt   = g_Wt[stage];

    float acc[4] = {0.f, 0.f, 0.f, 0.f};
    for (int kc = 0; kc < 4; kc++) {
        for (int i = t; i < 32 * 128; i += 256) {
            int cc = i >> 7, kk = i & 127;
            hs[i] = hin[(cbase + cc) * INF + kc * 128 + kk];
        }
        __syncthreads();
        const float* wp = Wt + (size_t)(kc * 128) * INF + o;
#pragma unroll 8
        for (int kk = 0; kk < 128; kk++) {
            float wv = wp[(size_t)kk * INF];
#pragma unroll
            for (int i = 0; i < 4; i++)
                acc[i] = fmaf(hs[(w * 4 + i) * 128 + kk], wv, acc[i]);
        }
        __syncthreads();
    }
    const float b = bias[o];
#pragma unroll
    for (int i = 0; i < 4; i++) {
        float v = acc[i] + b;
        if (silu) v = v * (1.f / (1.f + __expf(-v)));
        hout[(cbase + w * 4 + i) * INF + o] = v;
    }
}

// ============================================================================
// Stage 5: scatter out[p][:] = h_final[cid[p]][:].  64 points per block; cids
// staged in smem first so the store loop has no long-latency dependence.
// ============================================================================
__global__ void scatter_kernel(float* __restrict__ out) {
    __shared__ int sc[64];
    const int t = threadIdx.x;                 // 0..255
    const int p0 = blockIdx.x * 64;
    if (t < 64) sc[t] = g_cid[p0 + t];
    __syncthreads();
    const int pl = t >> 7;                     // 0 or 1
    const int f4 = t & 127;                    // float4 index within 512-float row
    const float4* h4 = (const float4*)g_hbuf[3];
    float4* o4 = (float4*)out;
#pragma unroll 8
    for (int i = pl; i < 64; i += 2) {
        int c = sc[i];
        o4[(size_t)(p0 + i) * 128 + f4] = h4[c * 128 + f4];
    }
}

// ============================================================================
extern "C" void kernel_launch(void* const* d_in, const int* in_sizes, int n_in,
                              void* d_out, int out_size) {
    const float* x  = (const float*)d_in[0];
    const float* V0 = (const float*)d_in[1];
    const float* g0 = (const float*)d_in[2];
    const float* b0 = (const float*)d_in[3];
    const float* V1 = (const float*)d_in[4];
    const float* g1 = (const float*)d_in[5];
    const float* b1 = (const float*)d_in[6];
    const float* Wf = (const float*)d_in[7];
    const float* bf = (const float*)d_in[8];
    float* out = (float*)d_out;

    const int red_smem = (NC * FCHUNK + NC) * (int)sizeof(float);   // 65792 B
    cudaFuncSetAttribute(reduce_kernel,
                         cudaFuncAttributeMaxDynamicSharedMemorySize, red_smem);

    // Launch order chosen so reduce_kernel sits at the ncu-captured position.
    norm_kernel<<<128, 256>>>(V0, g0, V1, g1);                  // 1
    prep_wt<<<dim3(16, 16, 2), dim3(32, 8)>>>(V0, V1, 0);       // 2: Wt0, Wt1
    prep_wt<<<dim3(16, 16, 1), dim3(32, 8)>>>(Wf, Wf, 2);       // 3: Wt2
    reduce_kernel<<<dim3(2, RBLOCKS), 256, red_smem>>>(x);      // 4  <-- profile me
    mean_kernel<<<NC, INF>>>();                                 // 5
    gemm_kernel<<<dim3(16, 2), 256>>>(0, b0, 1);                // 6
    gemm_kernel<<<dim3(16, 2), 256>>>(1, b1, 1);                // 7
    gemm_kernel<<<dim3(16, 2), 256>>>(2, bf, 0);                // 8
    scatter_kernel<<<2048, 256>>>(out);                         // 9
}

// round 8
// speedup vs baseline: 1.4654x; 1.3993x over previous
#include <cuda_runtime.h>

#define NPOINTS 131072
#define INF 512
#define NC 64
#define ROWSTRIDE 513   // 512 features + 1 case id per row of x
#define RBLOCKS 222     // point tiles: grid (2 x 222) = 444 = 148 SMs x 3 CTAs
#define FCHUNK 256      // features per reduce block

// -------- device scratch (static: no allocations allowed) --------
__device__ float g_part[RBLOCKS][NC][INF];     // per-tile partial sums (~29 MB)
__device__ float g_pcnt[RBLOCKS][NC];          // per-tile case counts
__device__ int   g_cid[NPOINTS];               // compact case ids (for scatter)
__device__ __align__(16) float g_hfinal[NC * INF];   // final MLP output table
__device__ float g_Wt[3][INF * INF];           // scaled transposed weights (k-major)

// ============================================================================
// Kernel 1: fused weight prep. Per block: load 32 rows of V (or Wf) to smem,
// compute weight-norm scales g/||row||, write scaled TRANSPOSED strip to g_Wt.
// grid (16 o-blocks, 3 matrices), 256 threads, 65.8 KB dynamic smem.
// ============================================================================
__global__ void prep_kernel(const float* __restrict__ V0, const float* __restrict__ g0,
                            const float* __restrict__ V1, const float* __restrict__ g1,
                            const float* __restrict__ Wf) {
    extern __shared__ float sm[];              // 32*513 row cache + 32 scales
    float* srow   = sm;
    float* sscale = sm + 32 * 513;
    const int m  = blockIdx.y;                 // 0:V0 1:V1 2:Wf
    const int ob = blockIdx.x * 32;
    const float* src = (m == 0) ? V0 : ((m == 1) ? V1 : Wf);
    const int t = threadIdx.x;

    for (int idx = t; idx < 32 * 512; idx += 256) {
        int r = idx >> 9, k = idx & 511;
        srow[r * 513 + k] = src[(size_t)(ob + r) * INF + k];
    }
    __syncthreads();

    const int w = t >> 5, lane = t & 31;
#pragma unroll
    for (int rr = 0; rr < 4; rr++) {
        int r = w * 4 + rr;
        float ss = 0.f;
        for (int k = lane; k < INF; k += 32) {
            float v = srow[r * 513 + k];
            ss = fmaf(v, v, ss);
        }
        for (int off = 16; off; off >>= 1) ss += __shfl_down_sync(0xffffffffu, ss, off);
        if (lane == 0) {
            float sc = 1.f;
            if (m == 0) sc = g0[ob + r] * rsqrtf(ss);
            else if (m == 1) sc = g1[ob + r] * rsqrtf(ss);
            sscale[r] = sc;
        }
    }
    __syncthreads();

    // transposed write: Wt[k][ob+lane] = row[lane][k] * scale[lane]
    const float scl = sscale[lane];
#pragma unroll 8
    for (int j = 0; j < 64; j++) {
        int k = w + 8 * j;
        g_Wt[m][(size_t)k * INF + ob + lane] = srow[lane * 513 + k] * scl;
    }
}

// ============================================================================
// Kernel 2: per-case partial sums. All 256 threads handle the SAME point each
// step -> thread t exclusively owns feature lane t of the smem accumulator:
// no atomics, no races. 16-point batch => 32 LDGs in flight; launch_bounds
// grants the ~64 registers that batch needs (R7 profile: regs=32 killed MLP).
// chunk==1 blocks persist cid to g_cid for the scatter stage.
// ============================================================================
__global__ __launch_bounds__(256, 3)
void reduce_kernel(const float* __restrict__ x) {
    extern __shared__ float sacc[];            // NC*FCHUNK accum + NC counts
    float* cnt = sacc + NC * FCHUNK;
    const int chunk = blockIdx.x;              // 0..1 -> feature half
    const int pt    = blockIdx.y;              // 0..RBLOCKS-1 -> point tile
    const int t     = threadIdx.x;             // 0..255
    const int cbase = chunk * FCHUNK;
    const bool count_owner = (chunk == 0 && t == 0);
    const bool cid_owner   = (chunk == 1 && t == 0);

    for (int i = t; i < NC * FCHUNK; i += 256) sacc[i] = 0.f;
    if (chunk == 0 && t < NC) cnt[t] = 0.f;
    __syncthreads();

    const int per = (NPOINTS + RBLOCKS - 1) / RBLOCKS;   // 591
    int p0 = pt * per;
    int p1 = p0 + per; if (p1 > NPOINTS) p1 = NPOINTS;

    int p = p0;
    for (; p + 16 <= p1; p += 16) {
        float v[16]; int c[16];
#pragma unroll
        for (int i = 0; i < 16; i++) {
            const float* row = x + (size_t)(p + i) * ROWSTRIDE;
            v[i] = __ldcs(row + cbase + t);
            c[i] = __float2int_rn(__ldcs(row + INF));   // cid: exact small int
        }
#pragma unroll
        for (int i = 0; i < 16; i++) sacc[c[i] * FCHUNK + t] += v[i];
        if (count_owner) {
#pragma unroll
            for (int i = 0; i < 16; i++) cnt[c[i]] += 1.f;
        }
        if (cid_owner) {
#pragma unroll
            for (int i = 0; i < 16; i++) g_cid[p + i] = c[i];
        }
    }
    for (; p < p1; p++) {
        const float* row = x + (size_t)p * ROWSTRIDE;
        int c = __float2int_rn(__ldcs(row + INF));
        sacc[c * FCHUNK + t] += __ldcs(row + cbase + t);
        if (count_owner) cnt[c] += 1.f;
        if (cid_owner) g_cid[p] = c;
    }
    __syncthreads();

    for (int i = t; i < NC * FCHUNK; i += 256) {
        int c = i >> 8;          // i / FCHUNK
        int f = i & (FCHUNK - 1);
        g_part[pt][c][cbase + f] = sacc[i];
    }
    if (chunk == 0 && t < NC) g_pcnt[pt][t] = cnt[t];
}

// ============================================================================
// Kernel 3: fused mean + 3-layer MLP. Cases are fully independent through the
// MLP, so block b owns cases 2b, 2b+1: reduce partials -> mean -> 3 chained
// matvec layers with smem-staged h (broadcast LDS) and coalesced weight LDGs.
// grid 32 blocks x 512 threads (thread t = output/feature t).
// ============================================================================
__global__ __launch_bounds__(512)
void mlp_kernel(const float* __restrict__ b0, const float* __restrict__ b1,
                const float* __restrict__ bf) {
    __shared__ float hs[2][INF];
    __shared__ float cnt2[2];
    const int t  = threadIdx.x;
    const int c0 = blockIdx.x * 2;

    // mean: 4 independent accumulators (2 tiles x 2 cases in flight)
    float x0 = 0.f, x1 = 0.f, y0 = 0.f, y1 = 0.f;
    int pt = 0;
    for (; pt + 2 <= RBLOCKS; pt += 2) {
        x0 += g_part[pt][c0][t];     y0 += g_part[pt][c0 + 1][t];
        x1 += g_part[pt + 1][c0][t]; y1 += g_part[pt + 1][c0 + 1][t];
    }
    for (; pt < RBLOCKS; pt++) { x0 += g_part[pt][c0][t]; y0 += g_part[pt][c0 + 1][t]; }

    if (t < 64) {
        int cl = t >> 5, l = t & 31;
        float cn = 0.f;
        for (int q = l; q < RBLOCKS; q += 32) cn += g_pcnt[q][c0 + cl];
        for (int off = 16; off; off >>= 1) cn += __shfl_down_sync(0xffffffffu, cn, off);
        if (l == 0) cnt2[cl] = fmaxf(cn, 1.f);
    }
    __syncthreads();
    hs[0][t] = (x0 + x1) / cnt2[0];
    hs[1][t] = (y0 + y1) / cnt2[1];
    __syncthreads();

    for (int L = 0; L < 3; L++) {
        const float* Wt = g_Wt[L];
        float a0 = 0.f, a1 = 0.f;
#pragma unroll 8
        for (int k = 0; k < INF; k++) {
            float wv = Wt[(size_t)k * INF + t];
            a0 = fmaf(hs[0][k], wv, a0);
            a1 = fmaf(hs[1][k], wv, a1);
        }
        const float* bb = (L == 0) ? b0 : ((L == 1) ? b1 : bf);
        float v0 = a0 + bb[t], v1 = a1 + bb[t];
        if (L < 2) {
            v0 = v0 * (1.f / (1.f + __expf(-v0)));
            v1 = v1 * (1.f / (1.f + __expf(-v1)));
            __syncthreads();
            hs[0][t] = v0; hs[1][t] = v1;
            __syncthreads();
        } else {
            g_hfinal[(size_t)c0 * INF + t]       = v0;
            g_hfinal[(size_t)(c0 + 1) * INF + t] = v1;
        }
    }
}

// ============================================================================
// Kernel 4: scatter out[p][:] = h_final[cid[p]][:].  64 points/block; cids
// staged in smem; float4 streaming stores (out is never re-read).
// ============================================================================
__global__ void scatter_kernel(float* __restrict__ out) {
    __shared__ int sc[64];
    const int t = threadIdx.x;                 // 0..255
    const int p0 = blockIdx.x * 64;
    if (t < 64) sc[t] = g_cid[p0 + t];
    __syncthreads();
    const int pl = t >> 7;                     // 0 or 1
    const int f4 = t & 127;                    // float4 index within 512-float row
    const float4* h4 = (const float4*)g_hfinal;
    float4* o4 = (float4*)out;
#pragma unroll 8
    for (int i = pl; i < 64; i += 2) {
        int c = sc[i];
        float4 v = h4[c * 128 + f4];
        __stcs(&o4[(size_t)(p0 + i) * 128 + f4], v);
    }
}

// ============================================================================
extern "C" void kernel_launch(void* const* d_in, const int* in_sizes, int n_in,
                              void* d_out, int out_size) {
    const float* x  = (const float*)d_in[0];
    const float* V0 = (const float*)d_in[1];
    const float* g0 = (const float*)d_in[2];
    const float* b0 = (const float*)d_in[3];
    const float* V1 = (const float*)d_in[4];
    const float* g1 = (const float*)d_in[5];
    const float* b1 = (const float*)d_in[6];
    const float* Wf = (const float*)d_in[7];
    const float* bf = (const float*)d_in[8];
    float* out = (float*)d_out;

    const int red_smem  = (NC * FCHUNK + NC) * (int)sizeof(float);  // 65792 B
    const int prep_smem = (32 * 513 + 32) * (int)sizeof(float);     // 65792 B
    cudaFuncSetAttribute(reduce_kernel,
                         cudaFuncAttributeMaxDynamicSharedMemorySize, red_smem);
    cudaFuncSetAttribute(prep_kernel,
                         cudaFuncAttributeMaxDynamicSharedMemorySize, prep_smem);

    // 4 launches; slot #4 (the ncu-captured one) = scatter.
    prep_kernel<<<dim3(16, 3), 256, prep_smem>>>(V0, g0, V1, g1, Wf);   // 1
    reduce_kernel<<<dim3(2, RBLOCKS), 256, red_smem>>>(x);              // 2
    mlp_kernel<<<32, 512>>>(b0, b1, bf);                                // 3
    scatter_kernel<<<2048, 256>>>(out);                                 // 4  <-- profile me
}